// round 16
// baseline (speedup 1.0000x reference)
#include <cuda_runtime.h>
#include <cuda_fp16.h>
#include <stdint.h>
#include <math.h>

#define N_TOK 8192
#define HDIM  1024
#define NEXP  16
#define TOPK  4
#define NPAIR (N_TOK * TOPK)
#define NBLK_TOPK (N_TOK / 256)       // 32
#define CHUNK 64
#define NCHUNK (HDIM / CHUNK)         // 16
#define MAXTILES 272

#define STAGE1 32768
#define NSTAGE1 3
#define G1_A  0
#define G1_BG 16384
#define G1_BU 24576
#define STAGE2 32768
#define NSTAGE2 3
#define G2_A 0
#define G2_B 16384
#define SMEM_MOE 98304

#define G1_BLOCKS (16 * MAXTILES)     // 4352
#define G2_BLOCKS (8 * MAXTILES)      // 2176
#define MOE_BLOCKS (G1_BLOCKS + G2_BLOCKS)

// prep roles
#define WQUARTER (NEXP * HDIM * HDIM / 4 / 4)   // 1048576 float4 per quarter
#define XQUARTER (N_TOK * HDIM / 4 / 4)         // 524288
#define PREP_W_BLOCKS (3 * WQUARTER / 256)      // 12288
#define PREP_X_BLOCKS (XQUARTER / 256)          // 2048
#define PREP_BLOCKS (PREP_W_BLOCKS + PREP_X_BLOCKS + NBLK_TOPK)

// ---------------- device scratch ----------------
__device__ int   g_counts[NEXP];
__device__ int   g_pairs[NEXP * NPAIR];
__device__ float g_partial[NBLK_TOPK * NEXP];
__device__ int   g_done;
__device__ int   g_ntiles;
__device__ int4  g_tiles[MAXTILES];   // (e, mbase, cnt, 0)
__device__ int   g_ready[MAXTILES];
__device__ __half g_X16[(size_t)N_TOK * HDIM];
__device__ __half g_Wg16[(size_t)NEXP * HDIM * HDIM];
__device__ __half g_Wu16[(size_t)NEXP * HDIM * HDIM];
__device__ __half g_Wd16[(size_t)NEXP * HDIM * HDIM];
__device__ __half g_t16[(size_t)NPAIR * HDIM];

// ---------------- helpers ----------------
__device__ __forceinline__ uint32_t smem_u32(const void* p) {
    uint32_t a;
    asm("{ .reg .u64 t; cvta.to.shared.u64 t, %1; cvt.u32.u64 %0, t; }" : "=r"(a) : "l"(p));
    return a;
}
__device__ __forceinline__ void ldm4(uint32_t* r, uint32_t a) {
    asm volatile("ldmatrix.sync.aligned.m8n8.x4.shared.b16 {%0,%1,%2,%3}, [%4];"
                 : "=r"(r[0]), "=r"(r[1]), "=r"(r[2]), "=r"(r[3]) : "r"(a));
}
__device__ __forceinline__ void mmaf16(float* d, const uint32_t* a, const uint32_t* b) {
    asm volatile("mma.sync.aligned.m16n8k16.row.col.f32.f16.f16.f32 "
                 "{%0,%1,%2,%3},{%4,%5,%6,%7},{%8,%9},{%0,%1,%2,%3};"
                 : "+f"(d[0]), "+f"(d[1]), "+f"(d[2]), "+f"(d[3])
                 : "r"(a[0]), "r"(a[1]), "r"(a[2]), "r"(a[3]), "r"(b[0]), "r"(b[1]));
}
#define CPA(dst, src, sz) asm volatile("cp.async.cg.shared.global [%0],[%1],16,%2;" :: "r"(dst), "l"(src), "r"(sz))
#define CPC()   asm volatile("cp.async.commit_group;")
#define CPW(n)  asm volatile("cp.async.wait_group %0;" :: "n"(n))

__device__ __forceinline__ uint2 pack4h(float4 v) {
    __half hx = __float2half_rn(v.x), hy = __float2half_rn(v.y);
    __half hz = __float2half_rn(v.z), hw = __float2half_rn(v.w);
    uint2 h;
    h.x = (uint32_t)__half_as_ushort(hx) | ((uint32_t)__half_as_ushort(hy) << 16);
    h.y = (uint32_t)__half_as_ushort(hz) | ((uint32_t)__half_as_ushort(hw) << 16);
    return h;
}

// ================= PREP: W/X convert + topk + aux + tiles, one launch ============
__global__ __launch_bounds__(256) void k_prep(const float4* __restrict__ X,
                                              const float4* __restrict__ Wg,
                                              const float4* __restrict__ Wu,
                                              const float4* __restrict__ Wd,
                                              const float* __restrict__ scores,
                                              float* __restrict__ dst) {
    const int bid = blockIdx.x;
    const int tid = threadIdx.x;

    if (bid < PREP_W_BLOCKS) {                      // ---- weight convert, MLP=4
        int which = bid / (WQUARTER / 256);
        int i = (bid % (WQUARTER / 256)) * 256 + tid;
        const float4* src = (which == 0) ? Wg : (which == 1) ? Wu : Wd;
        __half* dstw = (which == 0) ? g_Wg16 : (which == 1) ? g_Wu16 : g_Wd16;
        float4 v0 = src[i];
        float4 v1 = src[i + WQUARTER];
        float4 v2 = src[i + 2 * WQUARTER];
        float4 v3 = src[i + 3 * WQUARTER];
        ((uint2*)dstw)[i]                = pack4h(v0);
        ((uint2*)dstw)[i + WQUARTER]     = pack4h(v1);
        ((uint2*)dstw)[i + 2 * WQUARTER] = pack4h(v2);
        ((uint2*)dstw)[i + 3 * WQUARTER] = pack4h(v3);
        return;
    }
    if (bid < PREP_W_BLOCKS + PREP_X_BLOCKS) {      // ---- X convert, MLP=4
        int i = (bid - PREP_W_BLOCKS) * 256 + tid;
        float4 v0 = X[i];
        float4 v1 = X[i + XQUARTER];
        float4 v2 = X[i + 2 * XQUARTER];
        float4 v3 = X[i + 3 * XQUARTER];
        ((uint2*)g_X16)[i]                = pack4h(v0);
        ((uint2*)g_X16)[i + XQUARTER]     = pack4h(v1);
        ((uint2*)g_X16)[i + 2 * XQUARTER] = pack4h(v2);
        ((uint2*)g_X16)[i + 3 * XQUARTER] = pack4h(v3);
        return;
    }

    // ---- topk role (32 blocks)
    __shared__ float ssum[256][NEXP];
    __shared__ int ticket;
    const int blk = bid - PREP_W_BLOCKS - PREP_X_BLOCKS;
    const int n = blk * 256 + tid;
    float v[NEXP];
#pragma unroll
    for (int e = 0; e < NEXP; e++) v[e] = scores[(size_t)n * NEXP + e];
#pragma unroll
    for (int e = 0; e < NEXP; e++) ssum[tid][e] = v[e];
    bool used[NEXP];
#pragma unroll
    for (int e = 0; e < NEXP; e++) used[e] = false;
#pragma unroll
    for (int slot = 0; slot < TOPK; slot++) {
        float best = -1e30f; int bi = 0;
#pragma unroll
        for (int e = 0; e < NEXP; e++)
            if (!used[e] && v[e] > best) { best = v[e]; bi = e; }
        used[bi] = true;
        int pos = atomicAdd(&g_counts[bi], 1);
        g_pairs[bi * NPAIR + pos] = n * TOPK + slot;
    }
    __syncthreads();
    for (int s = 128; s > 0; s >>= 1) {
        if (tid < s)
#pragma unroll
            for (int e = 0; e < NEXP; e++) ssum[tid][e] += ssum[tid + s][e];
        __syncthreads();
    }
    if (tid < NEXP) g_partial[blk * NEXP + tid] = ssum[0][tid];

    __threadfence();
    if (tid == 0) ticket = atomicAdd(&g_done, 1);
    __syncthreads();
    if (ticket == NBLK_TOPK - 1) {
        __shared__ float se[NEXP];
        if (tid < NEXP) {
            float s = 0.0f;
            for (int b = 0; b < NBLK_TOPK; b++) s += g_partial[b * NEXP + tid];
            se[tid] = s * (float)g_counts[tid];
        }
        __syncthreads();
        if (tid == 0) {
            float t = 0.0f;
#pragma unroll
            for (int i = 0; i < NEXP; i++) t += se[i];
            dst[0] = t * (0.001f * (float)NEXP / ((float)N_TOK * (float)NPAIR));
            int tcount = 0;
            for (int ex = 0; ex < NEXP; ex++) {
                int c = g_counts[ex];
                for (int mb = 0; mb < c; mb += 128)
                    g_tiles[tcount++] = make_int4(ex, mb, c, 0);
            }
            g_ntiles = tcount;
            // pre-zero state for THIS launch's moe kernel and the next replay
            for (int i = 0; i < MAXTILES; i++) g_ready[i] = 0;
            for (int e = 0; e < NEXP; e++) g_counts[e] = 0;
            g_done = 0;
        }
    }
}

// ================= MOE: gemm1 tiles + flag-gated gemm2 tiles, one launch =========
__global__ __launch_bounds__(256, 2) void k_moe(float* __restrict__ out) {
    extern __shared__ char dyn[];
    __shared__ int spid[128];
    const int bid = blockIdx.x;
    const int tid = threadIdx.x;
    const uint32_t sbase = smem_u32(dyn);
    const int wid = tid >> 5, lane = tid & 31;
    const int lrr = tid >> 3, lcc = tid & 7;

    if (bid < G1_BLOCKS) {
        // ---------------- GEMM1 role: tile mt, n-slice nt ----------------
        const int mt = bid >> 4, nt = bid & 15;
        if (mt >= g_ntiles) return;
        const int4 te = g_tiles[mt];
        const int e = te.x, mbase = te.y, cnt = te.z;

        if (tid < 128) {
            int r = mbase + tid;
            spid[tid] = (r < cnt) ? g_pairs[e * NPAIR + r] : -1;
        }
        __syncthreads();

        const int n0 = nt * 64;
        const size_t eoff = (size_t)e * HDIM * HDIM;

        auto load_stage = [&](int s, int k0) {
            uint32_t st = sbase + s * STAGE1;
#pragma unroll
            for (int i = 0; i < 4; i++) {
                int rr = lrr + i * 32;
                int p = spid[rr];
                int tok = (p >= 0) ? (p >> 2) : 0;
                int sz = (p >= 0) ? 16 : 0;
                uint32_t sw = rr * 128 + ((lcc ^ (rr & 7)) << 4);
                CPA(st + G1_A + sw, g_X16 + (size_t)tok * HDIM + k0 + lcc * 8, sz);
            }
#pragma unroll
            for (int i = 0; i < 2; i++) {
                int rr = lrr + i * 32;
                size_t so = eoff + (size_t)(n0 + rr) * HDIM + k0 + lcc * 8;
                uint32_t sw = rr * 128 + ((lcc ^ (rr & 7)) << 4);
                CPA(st + G1_BG + sw, g_Wg16 + so, 16);
                CPA(st + G1_BU + sw, g_Wu16 + so, 16);
            }
            CPC();
        };

        const int wm = (wid & 3) * 32;
        const int wn = (wid >> 2) * 32;
        const int rA = wm + (lane & 15);
        const int alo = (lane >> 4) & 1;
        const int rB = wn + ((lane >> 4) & 1) * 8 + (lane & 7);
        const int blo = (lane >> 3) & 1;
        const int ra7 = rA & 7, rb7 = rB & 7;

        float accg[32], accu[32];
#pragma unroll
        for (int i = 0; i < 32; i++) { accg[i] = 0.f; accu[i] = 0.f; }

        load_stage(0, 0);
        load_stage(1, CHUNK);

        int s_cur = 0;
        for (int c = 0; c < NCHUNK; c++) {
            CPW(1);
            __syncthreads();
            if (c + 2 < NCHUNK) {
                int s2 = s_cur + 2; if (s2 >= NSTAGE1) s2 -= NSTAGE1;
                load_stage(s2, (c + 2) * CHUNK);
            } else CPC();

            uint32_t st = sbase + s_cur * STAGE1;
#pragma unroll
            for (int kk = 0; kk < 4; kk++) {
                uint32_t fA[8], fBG[8], fBU[8];
                uint32_t xa = (uint32_t)((kk * 2 + alo) ^ ra7) << 4;
                uint32_t xb = (uint32_t)((kk * 2 + blo) ^ rb7) << 4;
                ldm4(&fA[0], st + G1_A + rA * 128 + xa);
                ldm4(&fA[4], st + G1_A + (rA + 16) * 128 + xa);
                ldm4(&fBG[0], st + G1_BG + rB * 128 + xb);
                ldm4(&fBG[4], st + G1_BG + (rB + 16) * 128 + xb);
                ldm4(&fBU[0], st + G1_BU + rB * 128 + xb);
                ldm4(&fBU[4], st + G1_BU + (rB + 16) * 128 + xb);
#pragma unroll
                for (int mi = 0; mi < 2; mi++)
#pragma unroll
                    for (int ni = 0; ni < 4; ni++) {
                        mmaf16(&accg[(mi * 4 + ni) * 4], &fA[mi * 4], &fBG[ni * 2]);
                        mmaf16(&accu[(mi * 4 + ni) * 4], &fA[mi * 4], &fBU[ni * 2]);
                    }
            }
            s_cur = s_cur + 1; if (s_cur >= NSTAGE1) s_cur = 0;
        }

        const int r0 = wm + (lane >> 2);
        const int coff = (lane & 3) * 2;
#pragma unroll
        for (int mi = 0; mi < 2; mi++) {
#pragma unroll
            for (int half = 0; half < 2; half++) {
                int row = r0 + mi * 16 + half * 8;
                int p = spid[row];
                if (p < 0) continue;
#pragma unroll
                for (int ni = 0; ni < 4; ni++) {
                    int idx = mi * 4 + ni;
                    float g0 = accg[idx * 4 + half * 2 + 0];
                    float g1 = accg[idx * 4 + half * 2 + 1];
                    float u0 = accu[idx * 4 + half * 2 + 0];
                    float u1 = accu[idx * 4 + half * 2 + 1];
                    float v0 = u0 * g0 / (1.0f + __expf(-g0));
                    float v1 = u1 * g1 / (1.0f + __expf(-g1));
                    __half h0 = __float2half_rn(v0), h1 = __float2half_rn(v1);
                    uint32_t hp = (uint32_t)__half_as_ushort(h0) | ((uint32_t)__half_as_ushort(h1) << 16);
                    *(uint32_t*)(g_t16 + (size_t)p * HDIM + n0 + wn + ni * 8 + coff) = hp;
                }
            }
        }
        // signal completion of this (mt, nt) slice
        __threadfence();
        __syncthreads();
        if (tid == 0) atomicAdd(&g_ready[mt], 1);
        return;
    }

    // ---------------- GEMM2 role: tile mt2, n-slice nt2 ----------------
    {
        const int b2 = bid - G1_BLOCKS;
        const int mt = b2 >> 3, nt = b2 & 7;
        if (mt >= g_ntiles) return;
        const int4 te = g_tiles[mt];
        const int e = te.x, mbase = te.y, cnt = te.z;

        if (tid < 128) {
            int r = mbase + tid;
            spid[tid] = (r < cnt) ? g_pairs[e * NPAIR + r] : -1;
        }
        // wait for all 16 gemm1 slices of this m-tile
        if (tid == 0) {
            while (atomicAdd(&g_ready[mt], 0) < 16) __nanosleep(200);
        }
        __syncthreads();
        __threadfence();

        const int n0 = nt * 128;
        const size_t eoff = (size_t)e * HDIM * HDIM;

        auto load_stage = [&](int s, int k0) {
            uint32_t st = sbase + s * STAGE2;
#pragma unroll
            for (int i = 0; i < 4; i++) {
                int rr = lrr + i * 32;
                int p = spid[rr];
                int pp = (p >= 0) ? p : 0;
                int sz = (p >= 0) ? 16 : 0;
                uint32_t sw = rr * 128 + ((lcc ^ (rr & 7)) << 4);
                CPA(st + G2_A + sw, g_t16 + (size_t)pp * HDIM + k0 + lcc * 8, sz);
            }
#pragma unroll
            for (int i = 0; i < 4; i++) {
                int rr = lrr + i * 32;
                size_t so = eoff + (size_t)(n0 + rr) * HDIM + k0 + lcc * 8;
                uint32_t sw = rr * 128 + ((lcc ^ (rr & 7)) << 4);
                CPA(st + G2_B + sw, g_Wd16 + so, 16);
            }
            CPC();
        };

        const int wm = (wid & 3) * 32;
        const int wn = (wid >> 2) * 64;
        const int rA = wm + (lane & 15);
        const int alo = (lane >> 4) & 1;
        const int rB = wn + ((lane >> 4) & 1) * 8 + (lane & 7);
        const int blo = (lane >> 3) & 1;
        const int ra7 = rA & 7, rb7 = rB & 7;

        float acc[64];
#pragma unroll
        for (int i = 0; i < 64; i++) acc[i] = 0.f;

        load_stage(0, 0);
        load_stage(1, CHUNK);

        int s_cur = 0;
        for (int c = 0; c < NCHUNK; c++) {
            CPW(1);
            __syncthreads();
            if (c + 2 < NCHUNK) {
                int s2 = s_cur + 2; if (s2 >= NSTAGE2) s2 -= NSTAGE2;
                load_stage(s2, (c + 2) * CHUNK);
            } else CPC();

            uint32_t st = sbase + s_cur * STAGE2;
#pragma unroll
            for (int kk = 0; kk < 4; kk++) {
                uint32_t fA[8], fB[16];
                uint32_t xa = (uint32_t)((kk * 2 + alo) ^ ra7) << 4;
                uint32_t xb = (uint32_t)((kk * 2 + blo) ^ rb7) << 4;
                ldm4(&fA[0], st + G2_A + rA * 128 + xa);
                ldm4(&fA[4], st + G2_A + (rA + 16) * 128 + xa);
#pragma unroll
                for (int nj = 0; nj < 4; nj++)
                    ldm4(&fB[nj * 4], st + G2_B + (rB + nj * 16) * 128 + xb);
#pragma unroll
                for (int mi = 0; mi < 2; mi++)
#pragma unroll
                    for (int ni = 0; ni < 8; ni++)
                        mmaf16(&acc[(mi * 8 + ni) * 4], &fA[mi * 4], &fB[ni * 2]);
            }
            s_cur = s_cur + 1; if (s_cur >= NSTAGE2) s_cur = 0;
        }

        const int r0 = wm + (lane >> 2);
        const int coff = (lane & 3) * 2;
#pragma unroll
        for (int mi = 0; mi < 2; mi++) {
#pragma unroll
            for (int half = 0; half < 2; half++) {
                int row = r0 + mi * 16 + half * 8;
                int p = spid[row];
                if (p < 0) continue;
#pragma unroll
                for (int ni = 0; ni < 8; ni++) {
                    int idx = mi * 8 + ni;
                    float2 v;
                    v.x = fmaxf(acc[idx * 4 + half * 2 + 0], 0.f);
                    v.y = fmaxf(acc[idx * 4 + half * 2 + 1], 0.f);
                    *(float2*)(out + (size_t)p * HDIM + n0 + wn + ni * 8 + coff) = v;
                }
            }
        }
    }
}

// ---------------- launch ----------------
extern "C" void kernel_launch(void* const* d_in, const int* in_sizes, int n_in,
                              void* d_out, int out_size) {
    const float* X      = (const float*)d_in[0];
    const float* scores = (const float*)d_in[1];
    const float* Wg     = (const float*)d_in[2];
    const float* Wu     = (const float*)d_in[3];
    const float* Wd     = (const float*)d_in[4];
    float* out = (float*)d_out;

    cudaFuncSetAttribute(k_moe, cudaFuncAttributeMaxDynamicSharedMemorySize, SMEM_MOE);

    k_prep<<<PREP_BLOCKS, 256>>>((const float4*)X, (const float4*)Wg,
                                 (const float4*)Wu, (const float4*)Wd,
                                 scores, out + (out_size - 1));
    k_moe<<<MOE_BLOCKS, 256, SMEM_MOE>>>(out);
}

// round 17
// speedup vs baseline: 1.4961x; 1.4961x over previous
#include <cuda_runtime.h>
#include <cuda_fp16.h>
#include <stdint.h>
#include <math.h>

#define N_TOK 8192
#define HDIM  1024
#define NEXP  16
#define TOPK  4
#define NPAIR (N_TOK * TOPK)
#define NBLK_TOPK (N_TOK / 256)       // 32
#define CHUNK 64
#define NCHUNK (HDIM / CHUNK)         // 16
#define MAXTILES 272

#define STAGE1 32768
#define NSTAGE1 3
#define SMEM1 (NSTAGE1 * STAGE1)      // 98304
#define G1_A  0
#define G1_BG 16384
#define G1_BU 24576
#define STAGE2 32768
#define NSTAGE2 3
#define SMEM2 (NSTAGE2 * STAGE2)      // 98304
#define G2_A 0
#define G2_B 16384

// prep roles
#define WQUARTER (NEXP * HDIM * HDIM / 4 / 4)   // 1048576 float4 per quarter
#define XQUARTER (N_TOK * HDIM / 4 / 4)         // 524288
#define PREP_W_BLOCKS (3 * WQUARTER / 256)      // 12288
#define PREP_X_BLOCKS (XQUARTER / 256)          // 2048
#define PREP_BLOCKS (PREP_W_BLOCKS + PREP_X_BLOCKS + NBLK_TOPK)

// ---------------- device scratch ----------------
__device__ int   g_counts[NEXP];
__device__ int   g_pairs[NEXP * NPAIR];
__device__ float g_partial[NBLK_TOPK * NEXP];
__device__ int   g_done;
__device__ int   g_ntiles;
__device__ int4  g_tiles[MAXTILES];   // (e, mbase, cnt, 0)
__device__ __half g_X16[(size_t)N_TOK * HDIM];
__device__ __half g_Wg16[(size_t)NEXP * HDIM * HDIM];
__device__ __half g_Wu16[(size_t)NEXP * HDIM * HDIM];
__device__ __half g_Wd16[(size_t)NEXP * HDIM * HDIM];
__device__ __half g_t16[(size_t)NPAIR * HDIM];

// ---------------- helpers ----------------
__device__ __forceinline__ uint32_t smem_u32(const void* p) {
    uint32_t a;
    asm("{ .reg .u64 t; cvta.to.shared.u64 t, %1; cvt.u32.u64 %0, t; }" : "=r"(a) : "l"(p));
    return a;
}
__device__ __forceinline__ void ldm4(uint32_t* r, uint32_t a) {
    asm volatile("ldmatrix.sync.aligned.m8n8.x4.shared.b16 {%0,%1,%2,%3}, [%4];"
                 : "=r"(r[0]), "=r"(r[1]), "=r"(r[2]), "=r"(r[3]) : "r"(a));
}
__device__ __forceinline__ void mmaf16(float* d, const uint32_t* a, const uint32_t* b) {
    asm volatile("mma.sync.aligned.m16n8k16.row.col.f32.f16.f16.f32 "
                 "{%0,%1,%2,%3},{%4,%5,%6,%7},{%8,%9},{%0,%1,%2,%3};"
                 : "+f"(d[0]), "+f"(d[1]), "+f"(d[2]), "+f"(d[3])
                 : "r"(a[0]), "r"(a[1]), "r"(a[2]), "r"(a[3]), "r"(b[0]), "r"(b[1]));
}
#define CPA(dst, src, sz) asm volatile("cp.async.cg.shared.global [%0],[%1],16,%2;" :: "r"(dst), "l"(src), "r"(sz))
#define CPC()   asm volatile("cp.async.commit_group;")
#define CPW(n)  asm volatile("cp.async.wait_group %0;" :: "n"(n))

__device__ __forceinline__ uint2 pack4h(float4 v) {
    __half hx = __float2half_rn(v.x), hy = __float2half_rn(v.y);
    __half hz = __float2half_rn(v.z), hw = __float2half_rn(v.w);
    uint2 h;
    h.x = (uint32_t)__half_as_ushort(hx) | ((uint32_t)__half_as_ushort(hy) << 16);
    h.y = (uint32_t)__half_as_ushort(hz) | ((uint32_t)__half_as_ushort(hw) << 16);
    return h;
}

// ================= PREP: W/X convert + topk + aux + tiles, one launch ============
__global__ __launch_bounds__(256) void k_prep(const float4* __restrict__ X,
                                              const float4* __restrict__ Wg,
                                              const float4* __restrict__ Wu,
                                              const float4* __restrict__ Wd,
                                              const float* __restrict__ scores,
                                              float* __restrict__ dst) {
    const int bid = blockIdx.x;
    const int tid = threadIdx.x;

    if (bid < PREP_W_BLOCKS) {                      // ---- weight convert, MLP=4
        int which = bid / (WQUARTER / 256);
        int i = (bid % (WQUARTER / 256)) * 256 + tid;
        const float4* src = (which == 0) ? Wg : (which == 1) ? Wu : Wd;
        __half* dstw = (which == 0) ? g_Wg16 : (which == 1) ? g_Wu16 : g_Wd16;
        float4 v0 = src[i];
        float4 v1 = src[i + WQUARTER];
        float4 v2 = src[i + 2 * WQUARTER];
        float4 v3 = src[i + 3 * WQUARTER];
        ((uint2*)dstw)[i]                = pack4h(v0);
        ((uint2*)dstw)[i + WQUARTER]     = pack4h(v1);
        ((uint2*)dstw)[i + 2 * WQUARTER] = pack4h(v2);
        ((uint2*)dstw)[i + 3 * WQUARTER] = pack4h(v3);
        return;
    }
    if (bid < PREP_W_BLOCKS + PREP_X_BLOCKS) {      // ---- X convert, MLP=4
        int i = (bid - PREP_W_BLOCKS) * 256 + tid;
        float4 v0 = X[i];
        float4 v1 = X[i + XQUARTER];
        float4 v2 = X[i + 2 * XQUARTER];
        float4 v3 = X[i + 3 * XQUARTER];
        ((uint2*)g_X16)[i]                = pack4h(v0);
        ((uint2*)g_X16)[i + XQUARTER]     = pack4h(v1);
        ((uint2*)g_X16)[i + 2 * XQUARTER] = pack4h(v2);
        ((uint2*)g_X16)[i + 3 * XQUARTER] = pack4h(v3);
        return;
    }

    // ---- topk role (32 blocks)
    __shared__ float ssum[256][NEXP];
    __shared__ int ticket;
    const int blk = bid - PREP_W_BLOCKS - PREP_X_BLOCKS;
    const int n = blk * 256 + tid;
    float v[NEXP];
#pragma unroll
    for (int e = 0; e < NEXP; e++) v[e] = scores[(size_t)n * NEXP + e];
#pragma unroll
    for (int e = 0; e < NEXP; e++) ssum[tid][e] = v[e];
    bool used[NEXP];
#pragma unroll
    for (int e = 0; e < NEXP; e++) used[e] = false;
#pragma unroll
    for (int slot = 0; slot < TOPK; slot++) {
        float best = -1e30f; int bi = 0;
#pragma unroll
        for (int e = 0; e < NEXP; e++)
            if (!used[e] && v[e] > best) { best = v[e]; bi = e; }
        used[bi] = true;
        int pos = atomicAdd(&g_counts[bi], 1);
        g_pairs[bi * NPAIR + pos] = n * TOPK + slot;
    }
    __syncthreads();
    for (int s = 128; s > 0; s >>= 1) {
        if (tid < s)
#pragma unroll
            for (int e = 0; e < NEXP; e++) ssum[tid][e] += ssum[tid + s][e];
        __syncthreads();
    }
    if (tid < NEXP) g_partial[blk * NEXP + tid] = ssum[0][tid];

    __threadfence();
    if (tid == 0) ticket = atomicAdd(&g_done, 1);
    __syncthreads();
    if (ticket == NBLK_TOPK - 1) {
        __shared__ float se[NEXP];
        if (tid < NEXP) {
            float s = 0.0f;
            for (int b = 0; b < NBLK_TOPK; b++) s += g_partial[b * NEXP + tid];
            se[tid] = s * (float)g_counts[tid];
        }
        __syncthreads();
        if (tid == 0) {
            float t = 0.0f;
#pragma unroll
            for (int i = 0; i < NEXP; i++) t += se[i];
            dst[0] = t * (0.001f * (float)NEXP / ((float)N_TOK * (float)NPAIR));
            int tcount = 0;
            for (int ex = 0; ex < NEXP; ex++) {
                int c = g_counts[ex];
                for (int mb = 0; mb < c; mb += 128)
                    g_tiles[tcount++] = make_int4(ex, mb, c, 0);
            }
            g_ntiles = tcount;
            // pre-zero routing state for the next graph replay
            for (int e = 0; e < NEXP; e++) g_counts[e] = 0;
            g_done = 0;
        }
    }
}

// ---------------- GEMM1: gate+up fp16, M128xN64, 256thr, 2 CTAs/SM --------------
__global__ __launch_bounds__(256, 2) void k_gemm1() {
    if ((int)blockIdx.y >= g_ntiles) return;
    const int4 te = g_tiles[blockIdx.y];
    const int e = te.x, mbase = te.y, cnt = te.z;

    extern __shared__ char dyn[];
    __shared__ int spid[128];
    const int tid = threadIdx.x;
    if (tid < 128) {
        int r = mbase + tid;
        spid[tid] = (r < cnt) ? g_pairs[e * NPAIR + r] : -1;
    }
    __syncthreads();

    const uint32_t sbase = smem_u32(dyn);
    const int n0 = blockIdx.x * 64;
    const size_t eoff = (size_t)e * HDIM * HDIM;

    const int lrr = tid >> 3, lcc = tid & 7;

    auto load_stage = [&](int s, int k0) {
        uint32_t st = sbase + s * STAGE1;
#pragma unroll
        for (int i = 0; i < 4; i++) {
            int rr = lrr + i * 32;
            int p = spid[rr];
            int tok = (p >= 0) ? (p >> 2) : 0;
            int sz = (p >= 0) ? 16 : 0;
            uint32_t sw = rr * 128 + ((lcc ^ (rr & 7)) << 4);
            CPA(st + G1_A + sw, g_X16 + (size_t)tok * HDIM + k0 + lcc * 8, sz);
        }
#pragma unroll
        for (int i = 0; i < 2; i++) {
            int rr = lrr + i * 32;
            size_t so = eoff + (size_t)(n0 + rr) * HDIM + k0 + lcc * 8;
            uint32_t sw = rr * 128 + ((lcc ^ (rr & 7)) << 4);
            CPA(st + G1_BG + sw, g_Wg16 + so, 16);
            CPA(st + G1_BU + sw, g_Wu16 + so, 16);
        }
        CPC();
    };

    const int wid = tid >> 5, lane = tid & 31;
    const int wm = (wid & 3) * 32;
    const int wn = (wid >> 2) * 32;
    const int rA = wm + (lane & 15);
    const int alo = (lane >> 4) & 1;
    const int rB = wn + ((lane >> 4) & 1) * 8 + (lane & 7);
    const int blo = (lane >> 3) & 1;
    const int ra7 = rA & 7, rb7 = rB & 7;

    float accg[32], accu[32];
#pragma unroll
    for (int i = 0; i < 32; i++) { accg[i] = 0.f; accu[i] = 0.f; }

    load_stage(0, 0);
    load_stage(1, CHUNK);

    int s_cur = 0;
    for (int c = 0; c < NCHUNK; c++) {
        CPW(1);
        __syncthreads();
        if (c + 2 < NCHUNK) {
            int s2 = s_cur + 2; if (s2 >= NSTAGE1) s2 -= NSTAGE1;
            load_stage(s2, (c + 2) * CHUNK);
        } else CPC();

        uint32_t st = sbase + s_cur * STAGE1;
#pragma unroll
        for (int kk = 0; kk < 4; kk++) {
            uint32_t fA[8], fBG[8], fBU[8];
            uint32_t xa = (uint32_t)((kk * 2 + alo) ^ ra7) << 4;
            uint32_t xb = (uint32_t)((kk * 2 + blo) ^ rb7) << 4;
            ldm4(&fA[0], st + G1_A + rA * 128 + xa);
            ldm4(&fA[4], st + G1_A + (rA + 16) * 128 + xa);
            ldm4(&fBG[0], st + G1_BG + rB * 128 + xb);
            ldm4(&fBG[4], st + G1_BG + (rB + 16) * 128 + xb);
            ldm4(&fBU[0], st + G1_BU + rB * 128 + xb);
            ldm4(&fBU[4], st + G1_BU + (rB + 16) * 128 + xb);
#pragma unroll
            for (int mi = 0; mi < 2; mi++)
#pragma unroll
                for (int ni = 0; ni < 4; ni++) {
                    mmaf16(&accg[(mi * 4 + ni) * 4], &fA[mi * 4], &fBG[ni * 2]);
                    mmaf16(&accu[(mi * 4 + ni) * 4], &fA[mi * 4], &fBU[ni * 2]);
                }
        }
        s_cur = s_cur + 1; if (s_cur >= NSTAGE1) s_cur = 0;
    }

    const int r0 = wm + (lane >> 2);
    const int coff = (lane & 3) * 2;
#pragma unroll
    for (int mi = 0; mi < 2; mi++) {
#pragma unroll
        for (int half = 0; half < 2; half++) {
            int row = r0 + mi * 16 + half * 8;
            int p = spid[row];
            if (p < 0) continue;
#pragma unroll
            for (int ni = 0; ni < 4; ni++) {
                int idx = mi * 4 + ni;
                float g0 = accg[idx * 4 + half * 2 + 0];
                float g1 = accg[idx * 4 + half * 2 + 1];
                float u0 = accu[idx * 4 + half * 2 + 0];
                float u1 = accu[idx * 4 + half * 2 + 1];
                float v0 = u0 * g0 / (1.0f + __expf(-g0));
                float v1 = u1 * g1 / (1.0f + __expf(-g1));
                __half h0 = __float2half_rn(v0), h1 = __float2half_rn(v1);
                uint32_t hp = (uint32_t)__half_as_ushort(h0) | ((uint32_t)__half_as_ushort(h1) << 16);
                *(uint32_t*)(g_t16 + (size_t)p * HDIM + n0 + wn + ni * 8 + coff) = hp;
            }
        }
    }
}

// ---------------- GEMM2: down proj fp16, M128xN128, 256thr, 2 CTAs/SM, relu ------
__global__ __launch_bounds__(256, 2) void k_gemm2(float* __restrict__ out) {
    if ((int)blockIdx.y >= g_ntiles) return;
    const int4 te = g_tiles[blockIdx.y];
    const int e = te.x, mbase = te.y, cnt = te.z;

    extern __shared__ char dyn[];
    __shared__ int spid[128];
    const int tid = threadIdx.x;
    if (tid < 128) {
        int r = mbase + tid;
        spid[tid] = (r < cnt) ? g_pairs[e * NPAIR + r] : -1;
    }
    __syncthreads();

    const uint32_t sbase = smem_u32(dyn);
    const int n0 = blockIdx.x * 128;
    const size_t eoff = (size_t)e * HDIM * HDIM;

    const int lrr = tid >> 3, lcc = tid & 7;

    auto load_stage = [&](int s, int k0) {
        uint32_t st = sbase + s * STAGE2;
#pragma unroll
        for (int i = 0; i < 4; i++) {
            int rr = lrr + i * 32;
            int p = spid[rr];
            int pp = (p >= 0) ? p : 0;
            int sz = (p >= 0) ? 16 : 0;
            uint32_t sw = rr * 128 + ((lcc ^ (rr & 7)) << 4);
            CPA(st + G2_A + sw, g_t16 + (size_t)pp * HDIM + k0 + lcc * 8, sz);
        }
#pragma unroll
        for (int i = 0; i < 4; i++) {
            int rr = lrr + i * 32;
            size_t so = eoff + (size_t)(n0 + rr) * HDIM + k0 + lcc * 8;
            uint32_t sw = rr * 128 + ((lcc ^ (rr & 7)) << 4);
            CPA(st + G2_B + sw, g_Wd16 + so, 16);
        }
        CPC();
    };

    const int wid = tid >> 5, lane = tid & 31;
    const int wm = (wid & 3) * 32;
    const int wn = (wid >> 2) * 64;
    const int rA = wm + (lane & 15);
    const int alo = (lane >> 4) & 1;
    const int rB = wn + ((lane >> 4) & 1) * 8 + (lane & 7);
    const int blo = (lane >> 3) & 1;
    const int ra7 = rA & 7, rb7 = rB & 7;

    float acc[64];
#pragma unroll
    for (int i = 0; i < 64; i++) acc[i] = 0.f;

    load_stage(0, 0);
    load_stage(1, CHUNK);

    int s_cur = 0;
    for (int c = 0; c < NCHUNK; c++) {
        CPW(1);
        __syncthreads();
        if (c + 2 < NCHUNK) {
            int s2 = s_cur + 2; if (s2 >= NSTAGE2) s2 -= NSTAGE2;
            load_stage(s2, (c + 2) * CHUNK);
        } else CPC();

        uint32_t st = sbase + s_cur * STAGE2;
#pragma unroll
        for (int kk = 0; kk < 4; kk++) {
            uint32_t fA[8], fB[16];
            uint32_t xa = (uint32_t)((kk * 2 + alo) ^ ra7) << 4;
            uint32_t xb = (uint32_t)((kk * 2 + blo) ^ rb7) << 4;
            ldm4(&fA[0], st + G2_A + rA * 128 + xa);
            ldm4(&fA[4], st + G2_A + (rA + 16) * 128 + xa);
#pragma unroll
            for (int nj = 0; nj < 4; nj++)
                ldm4(&fB[nj * 4], st + G2_B + (rB + nj * 16) * 128 + xb);
#pragma unroll
            for (int mi = 0; mi < 2; mi++)
#pragma unroll
                for (int ni = 0; ni < 8; ni++)
                    mmaf16(&acc[(mi * 8 + ni) * 4], &fA[mi * 4], &fB[ni * 2]);
        }
        s_cur = s_cur + 1; if (s_cur >= NSTAGE2) s_cur = 0;
    }

    const int r0 = wm + (lane >> 2);
    const int coff = (lane & 3) * 2;
#pragma unroll
    for (int mi = 0; mi < 2; mi++) {
#pragma unroll
        for (int half = 0; half < 2; half++) {
            int row = r0 + mi * 16 + half * 8;
            int p = spid[row];
            if (p < 0) continue;
#pragma unroll
            for (int ni = 0; ni < 8; ni++) {
                int idx = mi * 8 + ni;
                float2 v;
                v.x = fmaxf(acc[idx * 4 + half * 2 + 0], 0.f);
                v.y = fmaxf(acc[idx * 4 + half * 2 + 1], 0.f);
                *(float2*)(out + (size_t)p * HDIM + n0 + wn + ni * 8 + coff) = v;
            }
        }
    }
}

// ---------------- launch ----------------
extern "C" void kernel_launch(void* const* d_in, const int* in_sizes, int n_in,
                              void* d_out, int out_size) {
    const float* X      = (const float*)d_in[0];
    const float* scores = (const float*)d_in[1];
    const float* Wg     = (const float*)d_in[2];
    const float* Wu     = (const float*)d_in[3];
    const float* Wd     = (const float*)d_in[4];
    float* out = (float*)d_out;

    cudaFuncSetAttribute(k_gemm1, cudaFuncAttributeMaxDynamicSharedMemorySize, SMEM1);
    cudaFuncSetAttribute(k_gemm2, cudaFuncAttributeMaxDynamicSharedMemorySize, SMEM2);

    k_prep<<<PREP_BLOCKS, 256>>>((const float4*)X, (const float4*)Wg,
                                 (const float4*)Wu, (const float4*)Wd,
                                 scores, out + (out_size - 1));

    dim3 g1(HDIM / 64, MAXTILES);    // (16, 272)
    k_gemm1<<<g1, 256, SMEM1>>>();

    dim3 g2(HDIM / 128, MAXTILES);   // (8, 272)
    k_gemm2<<<g2, 256, SMEM2>>>(out);
}